// round 1
// baseline (speedup 1.0000x reference)
#include <cuda_runtime.h>
#include <cstdint>

// ---------------------------------------------------------------------------
// Shapes
//   img      [64][3][416][416]
//   conv1    5x5 VALID -> [64][6][412][412] -> relu -> pool2 -> [64][6][206][206]
//   conv2    5x5 VALID -> [64][16][202][202] -> relu -> pool2 -> [64][16][101][101]
//   fc1      [64][163216] @ W1^T[163216][64] + b -> relu -> [64][64]
//   boxes    x.reshape(64,4,16).transpose(0,2,1) -> [1024][4]
//   roipool  -> [1024][3][16][16]
//   roi_conv 4x4 VALID -> [1024][1][13][13] -> relu
//   fc2      [1024][169] @ W2^T + b -> relu -> [1024][64]
// ---------------------------------------------------------------------------

__device__ float g_pool1[64 * 6 * 206 * 206];       // 65.2 MB
__device__ float g_pool2[64 * 16 * 101 * 101];      // 41.8 MB
__device__ float g_fc1part[101 * 64 * 64];          // split-K partials
__device__ float4 g_roi[1024];                      // (x1, y1, bw, bh)

// ---------------------------------------------------------------------------
// conv1 + relu + maxpool2: block = 16x16 pooled tile, 256 threads,
// each thread computes a 2x2 conv patch (one pooled output) for all 6 oc.
// ---------------------------------------------------------------------------
__global__ __launch_bounds__(256) void conv1_kernel(
    const float* __restrict__ img, const float* __restrict__ w,
    const float* __restrict__ bias) {
    __shared__ float sin[3][36 * 37];
    __shared__ float sw[450];
    __shared__ float sb[6];
    const int bz = blockIdx.z, by = blockIdx.y, bx = blockIdx.x;
    const int tid = threadIdx.x;

    for (int i = tid; i < 450; i += 256) sw[i] = w[i];
    if (tid < 6) sb[tid] = bias[tid];

    const int iy0 = by * 32, ix0 = bx * 32;
    for (int ic = 0; ic < 3; ic++) {
        const float* src = img + ((size_t)bz * 3 + ic) * 416 * 416;
        for (int e = tid; e < 36 * 36; e += 256) {
            int r = e / 36, c = e % 36;
            int gy = iy0 + r, gx = ix0 + c;
            float v = 0.f;
            if (gy < 416 && gx < 416) v = src[gy * 416 + gx];
            sin[ic][r * 37 + c] = v;
        }
    }
    __syncthreads();

    const int ty = tid >> 4, tx = tid & 15;
    float acc[6][4];
#pragma unroll
    for (int oc = 0; oc < 6; oc++) {
        acc[oc][0] = acc[oc][1] = acc[oc][2] = acc[oc][3] = 0.f;
    }
    const int base = (2 * ty) * 37 + 2 * tx;

    for (int ic = 0; ic < 3; ic++) {
        float in[6][6];
#pragma unroll
        for (int a = 0; a < 6; a++)
#pragma unroll
            for (int bb = 0; bb < 6; bb++) in[a][bb] = sin[ic][base + a * 37 + bb];
#pragma unroll
        for (int oc = 0; oc < 6; oc++) {
            const float* wp = &sw[(oc * 3 + ic) * 25];
#pragma unroll
            for (int ky = 0; ky < 5; ky++)
#pragma unroll
                for (int kx = 0; kx < 5; kx++) {
                    float wv = wp[ky * 5 + kx];
                    acc[oc][0] = fmaf(wv, in[ky][kx], acc[oc][0]);
                    acc[oc][1] = fmaf(wv, in[ky][kx + 1], acc[oc][1]);
                    acc[oc][2] = fmaf(wv, in[ky + 1][kx], acc[oc][2]);
                    acc[oc][3] = fmaf(wv, in[ky + 1][kx + 1], acc[oc][3]);
                }
        }
    }

    const int py = by * 16 + ty, px = bx * 16 + tx;
    if (py < 206 && px < 206) {
#pragma unroll
        for (int oc = 0; oc < 6; oc++) {
            float v = fmaxf(fmaxf(acc[oc][0], acc[oc][1]),
                            fmaxf(acc[oc][2], acc[oc][3]));
            g_pool1[(((size_t)bz * 6 + oc) * 206 + py) * 206 + px] =
                fmaxf(v + sb[oc], 0.f);
        }
    }
}

// ---------------------------------------------------------------------------
// conv2 + relu + maxpool2: block = 8x8 spatial x 4 oc-groups (256 threads).
// Each thread: one pooled output for 4 output channels (oc-group uniform per warp).
// ---------------------------------------------------------------------------
__global__ __launch_bounds__(256) void conv2_kernel(
    const float* __restrict__ w, const float* __restrict__ bias) {
    __shared__ float sin[6][20 * 21];
    __shared__ float sw[2400];
    __shared__ float sb[16];
    const int bz = blockIdx.z, by = blockIdx.y, bx = blockIdx.x;
    const int tid = threadIdx.x;

    for (int i = tid; i < 2400; i += 256) sw[i] = w[i];
    if (tid < 16) sb[tid] = bias[tid];

    const int iy0 = by * 16, ix0 = bx * 16;
    for (int e = tid; e < 6 * 400; e += 256) {
        int ic = e / 400, rem = e % 400, r = rem / 20, c = rem % 20;
        int gy = iy0 + r, gx = ix0 + c;
        float v = 0.f;
        if (gy < 206 && gx < 206)
            v = g_pool1[(((size_t)bz * 6 + ic) * 206 + gy) * 206 + gx];
        sin[ic][r * 21 + c] = v;
    }
    __syncthreads();

    const int ocg = tid >> 6;   // warp-uniform
    const int sp = tid & 63;
    const int ty = sp >> 3, tx = sp & 7;
    float acc[4][4];
#pragma unroll
    for (int j = 0; j < 4; j++)
        acc[j][0] = acc[j][1] = acc[j][2] = acc[j][3] = 0.f;
    const int base = (2 * ty) * 21 + 2 * tx;

    for (int ic = 0; ic < 6; ic++) {
        float in[6][6];
#pragma unroll
        for (int a = 0; a < 6; a++)
#pragma unroll
            for (int bb = 0; bb < 6; bb++) in[a][bb] = sin[ic][base + a * 21 + bb];
#pragma unroll
        for (int j = 0; j < 4; j++) {
            const int oc = ocg * 4 + j;
            const float* wp = &sw[(oc * 6 + ic) * 25];
#pragma unroll
            for (int ky = 0; ky < 5; ky++)
#pragma unroll
                for (int kx = 0; kx < 5; kx++) {
                    float wv = wp[ky * 5 + kx];
                    acc[j][0] = fmaf(wv, in[ky][kx], acc[j][0]);
                    acc[j][1] = fmaf(wv, in[ky][kx + 1], acc[j][1]);
                    acc[j][2] = fmaf(wv, in[ky + 1][kx], acc[j][2]);
                    acc[j][3] = fmaf(wv, in[ky + 1][kx + 1], acc[j][3]);
                }
        }
    }

    const int py = by * 8 + ty, px = bx * 8 + tx;
    if (py < 101 && px < 101) {
#pragma unroll
        for (int j = 0; j < 4; j++) {
            const int oc = ocg * 4 + j;
            float v = fmaxf(fmaxf(acc[j][0], acc[j][1]),
                            fmaxf(acc[j][2], acc[j][3]));
            g_pool2[(((size_t)bz * 16 + oc) * 101 + py) * 101 + px] =
                fmaxf(v + sb[oc], 0.f);
        }
    }
}

// ---------------------------------------------------------------------------
// fc1 split-K: 101 blocks, each reduces a 1616-long K-chunk of the
// 64x64x163216 GEMM, writing a 64x64 partial. 256 threads as 16x16,
// 4x4 register tile per thread.
// ---------------------------------------------------------------------------
__global__ __launch_bounds__(256) void fc1_kernel(const float* __restrict__ w) {
    __shared__ float xs[64][17];
    __shared__ float ws[64][17];
    const int blk = blockIdx.x;            // 0..100
    const int tid = threadIdx.x;
    const int tb = tid >> 4, to = tid & 15;
    float acc[4][4];
#pragma unroll
    for (int i = 0; i < 4; i++)
#pragma unroll
        for (int j = 0; j < 4; j++) acc[i][j] = 0.f;

    const int k0 = blk * 1616;
    for (int s = 0; s < 101; s++) {
        const int kbase = k0 + s * 16;
#pragma unroll
        for (int i = 0; i < 4; i++) {
            int e = tid + i * 256;
            int row = e >> 4, col = e & 15;
            xs[row][col] = g_pool2[(size_t)row * 163216 + kbase + col];
            ws[row][col] = w[(size_t)row * 163216 + kbase + col];
        }
        __syncthreads();
#pragma unroll
        for (int kk = 0; kk < 16; kk++) {
            float xr[4], wr[4];
#pragma unroll
            for (int i = 0; i < 4; i++) xr[i] = xs[tb + 16 * i][kk];
#pragma unroll
            for (int j = 0; j < 4; j++) wr[j] = ws[to + 16 * j][kk];
#pragma unroll
            for (int i = 0; i < 4; i++)
#pragma unroll
                for (int j = 0; j < 4; j++)
                    acc[i][j] = fmaf(xr[i], wr[j], acc[i][j]);
        }
        __syncthreads();
    }

    float* outp = g_fc1part + (size_t)blk * 4096;
#pragma unroll
    for (int i = 0; i < 4; i++)
#pragma unroll
        for (int j = 0; j < 4; j++)
            outp[(tb + 16 * i) * 64 + (to + 16 * j)] = acc[i][j];
}

// ---------------------------------------------------------------------------
// fc1 finalize + box decode. 1024 threads, one per roi.
// x[b][j] = relu(sum_s part[s][b][j] + fc1_b[j]); coords j = c*16 + i.
// Box math matches jnp exactly: rintf (round-half-even), clip to [0,415].
// ---------------------------------------------------------------------------
__global__ __launch_bounds__(256) void fc1_finalize_boxes(
    const float* __restrict__ fc1_b) {
    const int n = blockIdx.x * 256 + threadIdx.x;   // 0..1023
    const int b = n >> 4, i = n & 15;
    float v[4];
#pragma unroll
    for (int c = 0; c < 4; c++) {
        const int j = c * 16 + i;
        float s = 0.f;
        for (int t = 0; t < 101; t++) s += g_fc1part[t * 4096 + b * 64 + j];
        v[c] = fmaxf(s + fc1_b[j], 0.f);
    }
    float x1 = fminf(fmaxf(rintf(v[0] * 0.5f), 0.f), 415.f);
    float y1 = fminf(fmaxf(rintf(v[1] * 0.5f), 0.f), 415.f);
    float x2 = fminf(fmaxf(rintf(v[2] * 0.5f), 0.f), 415.f);
    float y2 = fminf(fmaxf(rintf(v[3] * 0.5f), 0.f), 415.f);
    float bw = fmaxf(x2 - x1 + 1.f, 1.f) * (1.f / 16.f);
    float bh = fmaxf(y2 - y1 + 1.f, 1.f) * (1.f / 16.f);
    g_roi[n] = make_float4(x1, y1, bw, bh);
}

// ---------------------------------------------------------------------------
// Fused RoIPool + 4x4 conv + fc2. One block per roi (1024 blocks, 256 thr).
// Each thread: one 16x16 bin (all 3 channels). Then 169 threads do the conv,
// 64 threads do fc2.
// ---------------------------------------------------------------------------
__global__ __launch_bounds__(256) void roi_kernel(
    const float* __restrict__ img, const float* __restrict__ rw,
    const float* __restrict__ rb, const float* __restrict__ w2,
    const float* __restrict__ b2, float* __restrict__ out) {
    __shared__ float pooled[3][16][16];
    __shared__ float yv[169];
    __shared__ float swc[48];
    __shared__ float sbc;
    const int n = blockIdx.x, tid = threadIdx.x;

    if (tid < 48) swc[tid] = rw[tid];
    if (tid == 0) sbc = rb[0];

    const float4 p = g_roi[n];   // x1, y1, bw, bh
    const int b = n >> 4;
    const int ph = tid >> 4, pw = tid & 15;

    const int hs = (int)fminf(floorf((float)ph * p.w) + p.y, 416.f);
    const int he = (int)fminf(ceilf((float)(ph + 1) * p.w) + p.y, 416.f);
    const int wsb = (int)fminf(floorf((float)pw * p.z) + p.x, 416.f);
    const int web = (int)fminf(ceilf((float)(pw + 1) * p.z) + p.x, 416.f);

    float m0, m1, m2;
    if (he > hs && web > wsb) {
        m0 = m1 = m2 = -3.4e38f;
        const float* c0 = img + (size_t)b * 3 * 416 * 416;
        for (int yy = hs; yy < he; yy++) {
            const float* row = c0 + yy * 416;
            for (int xx = wsb; xx < web; xx++) {
                m0 = fmaxf(m0, row[xx]);
                m1 = fmaxf(m1, row[xx + 416 * 416]);
                m2 = fmaxf(m2, row[xx + 2 * 416 * 416]);
            }
        }
    } else {
        m0 = m1 = m2 = 0.f;
    }
    pooled[0][ph][pw] = m0;
    pooled[1][ph][pw] = m1;
    pooled[2][ph][pw] = m2;
    __syncthreads();

    if (tid < 169) {
        const int oy = tid / 13, ox = tid % 13;
        float s = sbc;
#pragma unroll
        for (int c = 0; c < 3; c++)
#pragma unroll
            for (int ky = 0; ky < 4; ky++)
#pragma unroll
                for (int kx = 0; kx < 4; kx++)
                    s = fmaf(pooled[c][oy + ky][ox + kx],
                             swc[(c * 4 + ky) * 4 + kx], s);
        yv[tid] = fmaxf(s, 0.f);
    }
    __syncthreads();

    if (tid < 64) {
        float s = b2[tid];
        const float* wr = w2 + tid * 169;
        for (int pp = 0; pp < 169; pp++) s = fmaf(yv[pp], __ldg(&wr[pp]), s);
        out[(size_t)n * 64 + tid] = fmaxf(s, 0.f);
    }
}

// ---------------------------------------------------------------------------
extern "C" void kernel_launch(void* const* d_in, const int* in_sizes, int n_in,
                              void* d_out, int out_size) {
    const float* img     = (const float*)d_in[0];
    const float* conv1_w = (const float*)d_in[1];
    const float* conv1_b = (const float*)d_in[2];
    const float* conv2_w = (const float*)d_in[3];
    const float* conv2_b = (const float*)d_in[4];
    const float* fc1_w   = (const float*)d_in[5];
    const float* fc1_b   = (const float*)d_in[6];
    const float* roi_w   = (const float*)d_in[7];
    const float* roi_b   = (const float*)d_in[8];
    const float* fc2_w   = (const float*)d_in[9];
    const float* fc2_b   = (const float*)d_in[10];
    float* out = (float*)d_out;

    dim3 g1(13, 13, 64);
    conv1_kernel<<<g1, 256>>>(img, conv1_w, conv1_b);

    dim3 g2(13, 13, 64);
    conv2_kernel<<<g2, 256>>>(conv2_w, conv2_b);

    fc1_kernel<<<101, 256>>>(fc1_w);
    fc1_finalize_boxes<<<4, 256>>>(fc1_b);
    roi_kernel<<<1024, 256>>>(img, roi_w, roi_b, fc2_w, fc2_b, out);
}

// round 2
// speedup vs baseline: 1.1685x; 1.1685x over previous
#include <cuda_runtime.h>
#include <cstdint>

typedef unsigned long long ull;

// ---------------------------------------------------------------------------
// Shapes
//   img      [64][3][416][416]
//   conv1    5x5 VALID -> relu -> pool2 -> [64][6][206][206]
//   conv2    5x5 VALID -> relu -> pool2 -> [64][16][101][101]
//   fc1      [64][163216] -> relu -> [64][64] -> boxes [1024][4]
//   roipool  -> [1024][3][16][16] -> 4x4 conv -> relu -> fc2 -> [1024][64]
// ---------------------------------------------------------------------------

__device__ float g_pool1[64 * 6 * 206 * 206];
__device__ float g_pool2[64 * 16 * 101 * 101];
__device__ float g_fc1part[101 * 64 * 64];
__device__ float4 g_roi[1024];

// ---- packed fp32x2 helpers (sm_100a FFMA2) --------------------------------
__device__ __forceinline__ ull fma2(ull a, ull b, ull c) {
    ull d;
    asm("fma.rn.f32x2 %0, %1, %2, %3;" : "=l"(d) : "l"(a), "l"(b), "l"(c));
    return d;
}
__device__ __forceinline__ ull dup2(float v) {
    ull d;
    asm("mov.b64 %0, {%1, %1};" : "=l"(d) : "f"(v));
    return d;
}
__device__ __forceinline__ float2 unpk(ull a) {
    float2 r;
    asm("mov.b64 {%0, %1}, %2;" : "=f"(r.x), "=f"(r.y) : "l"(a));
    return r;
}

// ---------------------------------------------------------------------------
// conv1 + relu + maxpool2.
// Block: pooled tile 16(rows) x 32(cols). 256 threads = 16x16; each thread
// computes 2 adjacent pooled outputs (2x4 conv patch) for all 6 oc.
// f32x2 packing over oc-pairs (3 pairs); weights pre-paired in smem float2.
// ---------------------------------------------------------------------------
__global__ __launch_bounds__(256) void conv1_kernel(
    const float* __restrict__ img, const float* __restrict__ w,
    const float* __restrict__ bias) {
    __shared__ float sin[3][36 * 69];
    __shared__ float2 swp[3 * 25 * 3];   // [(ic*25+k)*3 + p]
    __shared__ float sb[6];
    const int bz = blockIdx.z, by = blockIdx.y, bx = blockIdx.x;
    const int tid = threadIdx.x;

    if (tid < 225) {
        int p = tid % 3, ick = tid / 3;          // ick = ic*25+k
        int ic = ick / 25, k = ick % 25;
        swp[tid] = make_float2(w[(2 * p) * 75 + ic * 25 + k],
                               w[(2 * p + 1) * 75 + ic * 25 + k]);
    }
    if (tid < 6) sb[tid] = bias[tid];

    const int iy0 = by * 32, ix0 = bx * 64;
    for (int e = tid; e < 3 * 36 * 68; e += 256) {
        int ic = e / 2448, rem = e % 2448, r = rem / 68, c = rem % 68;
        int gy = iy0 + r, gx = ix0 + c;
        float v = 0.f;
        if (gy < 416 && gx < 416)
            v = img[((size_t)bz * 3 + ic) * 416 * 416 + gy * 416 + gx];
        sin[ic][r * 69 + c] = v;
    }
    __syncthreads();

    const int ty = tid >> 4, tx = tid & 15;
    ull acc[3][2][4];
#pragma unroll
    for (int p = 0; p < 3; p++)
#pragma unroll
        for (int r = 0; r < 2; r++)
#pragma unroll
            for (int c = 0; c < 4; c++) acc[p][r][c] = 0ull;

    for (int ic = 0; ic < 3; ic++) {
        const float* S = &sin[ic][(2 * ty) * 69 + 4 * tx];
        const ull* W = (const ull*)&swp[ic * 75];
        ull RA[8], RB[8];
#pragma unroll
        for (int c = 0; c < 8; c++) RA[c] = dup2(S[c]);
#pragma unroll
        for (int ky = 0; ky < 5; ky++) {
            const float* Srow = S + (ky + 1) * 69;
#pragma unroll
            for (int c = 0; c < 8; c++) RB[c] = dup2(Srow[c]);
#pragma unroll
            for (int kx = 0; kx < 5; kx++) {
#pragma unroll
                for (int p = 0; p < 3; p++) {
                    ull wv = W[(ky * 5 + kx) * 3 + p];
#pragma unroll
                    for (int c = 0; c < 4; c++) {
                        acc[p][0][c] = fma2(RA[kx + c], wv, acc[p][0][c]);
                        acc[p][1][c] = fma2(RB[kx + c], wv, acc[p][1][c]);
                    }
                }
            }
#pragma unroll
            for (int c = 0; c < 8; c++) RA[c] = RB[c];
        }
    }

    const int py = by * 16 + ty;
    if (py < 206) {
#pragma unroll
        for (int d = 0; d < 2; d++) {
            const int px = bx * 32 + 2 * tx + d;
            if (px < 206) {
#pragma unroll
                for (int p = 0; p < 3; p++) {
                    float2 a00 = unpk(acc[p][0][2 * d]);
                    float2 a01 = unpk(acc[p][0][2 * d + 1]);
                    float2 a10 = unpk(acc[p][1][2 * d]);
                    float2 a11 = unpk(acc[p][1][2 * d + 1]);
                    float vlo = fmaxf(fmaxf(a00.x, a01.x), fmaxf(a10.x, a11.x));
                    float vhi = fmaxf(fmaxf(a00.y, a01.y), fmaxf(a10.y, a11.y));
                    g_pool1[(((size_t)bz * 6 + 2 * p) * 206 + py) * 206 + px] =
                        fmaxf(vlo + sb[2 * p], 0.f);
                    g_pool1[(((size_t)bz * 6 + 2 * p + 1) * 206 + py) * 206 + px] =
                        fmaxf(vhi + sb[2 * p + 1], 0.f);
                }
            }
        }
    }
}

// ---------------------------------------------------------------------------
// conv2 + relu + maxpool2.
// Block: pooled tile 16x16, 16 oc. 256 threads = 2 oc-groups x (16x8);
// each thread: 2 pooled outputs (2x4 conv patch) for 8 oc (4 oc-pairs).
// ---------------------------------------------------------------------------
__global__ __launch_bounds__(256) void conv2_kernel(
    const float* __restrict__ w, const float* __restrict__ bias) {
    __shared__ float sin[6][36 * 37];
    __shared__ float2 swp[6 * 25 * 8];   // [(ic*25+k)*8 + p]
    __shared__ float sb[16];
    const int bz = blockIdx.z, by = blockIdx.y, bx = blockIdx.x;
    const int tid = threadIdx.x;

    for (int i = tid; i < 1200; i += 256) {
        int p = i % 8, ick = i / 8;
        int ic = ick / 25, k = ick % 25;
        swp[i] = make_float2(w[((2 * p) * 6 + ic) * 25 + k],
                             w[((2 * p + 1) * 6 + ic) * 25 + k]);
    }
    if (tid < 16) sb[tid] = bias[tid];

    const int iy0 = by * 32, ix0 = bx * 32;
    for (int e = tid; e < 6 * 36 * 36; e += 256) {
        int ic = e / 1296, rem = e % 1296, r = rem / 36, c = rem % 36;
        int gy = iy0 + r, gx = ix0 + c;
        float v = 0.f;
        if (gy < 206 && gx < 206)
            v = g_pool1[(((size_t)bz * 6 + ic) * 206 + gy) * 206 + gx];
        sin[ic][r * 37 + c] = v;
    }
    __syncthreads();

    const int og = tid >> 7;            // 0..1 -> oc base 8*og
    const int t = tid & 127;
    const int ty = t >> 3, tx = t & 7;
    ull acc[4][2][4];
#pragma unroll
    for (int p = 0; p < 4; p++)
#pragma unroll
        for (int r = 0; r < 2; r++)
#pragma unroll
            for (int c = 0; c < 4; c++) acc[p][r][c] = 0ull;

    for (int ic = 0; ic < 6; ic++) {
        const float* S = &sin[ic][(2 * ty) * 37 + 4 * tx];
        const ull* W = (const ull*)&swp[ic * 200 + 4 * og];
        ull RA[8], RB[8];
#pragma unroll
        for (int c = 0; c < 8; c++) RA[c] = dup2(S[c]);
#pragma unroll
        for (int ky = 0; ky < 5; ky++) {
            const float* Srow = S + (ky + 1) * 37;
#pragma unroll
            for (int c = 0; c < 8; c++) RB[c] = dup2(Srow[c]);
#pragma unroll
            for (int kx = 0; kx < 5; kx++) {
#pragma unroll
                for (int p = 0; p < 4; p++) {
                    ull wv = W[(ky * 5 + kx) * 8 + p];
#pragma unroll
                    for (int c = 0; c < 4; c++) {
                        acc[p][0][c] = fma2(RA[kx + c], wv, acc[p][0][c]);
                        acc[p][1][c] = fma2(RB[kx + c], wv, acc[p][1][c]);
                    }
                }
            }
#pragma unroll
            for (int c = 0; c < 8; c++) RA[c] = RB[c];
        }
    }

    const int py = by * 16 + ty;
    if (py < 101) {
#pragma unroll
        for (int d = 0; d < 2; d++) {
            const int px = bx * 16 + 2 * tx + d;
            if (px < 101) {
#pragma unroll
                for (int p = 0; p < 4; p++) {
                    const int oc = 8 * og + 2 * p;
                    float2 a00 = unpk(acc[p][0][2 * d]);
                    float2 a01 = unpk(acc[p][0][2 * d + 1]);
                    float2 a10 = unpk(acc[p][1][2 * d]);
                    float2 a11 = unpk(acc[p][1][2 * d + 1]);
                    float vlo = fmaxf(fmaxf(a00.x, a01.x), fmaxf(a10.x, a11.x));
                    float vhi = fmaxf(fmaxf(a00.y, a01.y), fmaxf(a10.y, a11.y));
                    g_pool2[(((size_t)bz * 16 + oc) * 101 + py) * 101 + px] =
                        fmaxf(vlo + sb[oc], 0.f);
                    g_pool2[(((size_t)bz * 16 + oc + 1) * 101 + py) * 101 + px] =
                        fmaxf(vhi + sb[oc + 1], 0.f);
                }
            }
        }
    }
}

// ---------------------------------------------------------------------------
// fc1 split-K: 101 blocks, 64x64 partial each over a 1616-long K-chunk.
// ---------------------------------------------------------------------------
__global__ __launch_bounds__(256) void fc1_kernel(const float* __restrict__ w) {
    __shared__ float xs[64][17];
    __shared__ float ws[64][17];
    const int blk = blockIdx.x;
    const int tid = threadIdx.x;
    const int tb = tid >> 4, to = tid & 15;
    float acc[4][4];
#pragma unroll
    for (int i = 0; i < 4; i++)
#pragma unroll
        for (int j = 0; j < 4; j++) acc[i][j] = 0.f;

    const int k0 = blk * 1616;
    for (int s = 0; s < 101; s++) {
        const int kbase = k0 + s * 16;
#pragma unroll
        for (int i = 0; i < 4; i++) {
            int e = tid + i * 256;
            int row = e >> 4, col = e & 15;
            xs[row][col] = g_pool2[(size_t)row * 163216 + kbase + col];
            ws[row][col] = w[(size_t)row * 163216 + kbase + col];
        }
        __syncthreads();
#pragma unroll
        for (int kk = 0; kk < 16; kk++) {
            float xr[4], wr[4];
#pragma unroll
            for (int i = 0; i < 4; i++) xr[i] = xs[tb + 16 * i][kk];
#pragma unroll
            for (int j = 0; j < 4; j++) wr[j] = ws[to + 16 * j][kk];
#pragma unroll
            for (int i = 0; i < 4; i++)
#pragma unroll
                for (int j = 0; j < 4; j++)
                    acc[i][j] = fmaf(xr[i], wr[j], acc[i][j]);
        }
        __syncthreads();
    }

    float* outp = g_fc1part + (size_t)blk * 4096;
#pragma unroll
    for (int i = 0; i < 4; i++)
#pragma unroll
        for (int j = 0; j < 4; j++)
            outp[(tb + 16 * i) * 64 + (to + 16 * j)] = acc[i][j];
}

// ---------------------------------------------------------------------------
// fc1 finalize + box decode. 64 blocks (one per batch row), 256 threads:
// coalesced parallel reduction over the 101 partials.
// ---------------------------------------------------------------------------
__global__ __launch_bounds__(256) void fc1_finalize_boxes(
    const float* __restrict__ fc1_b) {
    __shared__ float partial[4][64];
    __shared__ float xv[64];
    const int b = blockIdx.x;
    const int tid = threadIdx.x;
    const int j = tid & 63, ch = tid >> 6;
    float s = 0.f;
    for (int t = ch; t < 101; t += 4)
        s += g_fc1part[t * 4096 + b * 64 + j];
    partial[ch][j] = s;
    __syncthreads();
    if (tid < 64) {
        float v = partial[0][tid] + partial[1][tid] + partial[2][tid] +
                  partial[3][tid] + fc1_b[tid];
        xv[tid] = fmaxf(v, 0.f);
    }
    __syncthreads();
    if (tid < 16) {
        const int i = tid;
        float x1 = fminf(fmaxf(rintf(xv[i] * 0.5f), 0.f), 415.f);
        float y1 = fminf(fmaxf(rintf(xv[16 + i] * 0.5f), 0.f), 415.f);
        float x2 = fminf(fmaxf(rintf(xv[32 + i] * 0.5f), 0.f), 415.f);
        float y2 = fminf(fmaxf(rintf(xv[48 + i] * 0.5f), 0.f), 415.f);
        float bw = fmaxf(x2 - x1 + 1.f, 1.f) * (1.f / 16.f);
        float bh = fmaxf(y2 - y1 + 1.f, 1.f) * (1.f / 16.f);
        g_roi[b * 16 + i] = make_float4(x1, y1, bw, bh);
    }
}

// ---------------------------------------------------------------------------
// Fused RoIPool + 4x4 conv + fc2. One block per roi.
// ---------------------------------------------------------------------------
__global__ __launch_bounds__(256) void roi_kernel(
    const float* __restrict__ img, const float* __restrict__ rw,
    const float* __restrict__ rb, const float* __restrict__ w2,
    const float* __restrict__ b2, float* __restrict__ out) {
    __shared__ float pooled[3][16][16];
    __shared__ float yv[169];
    __shared__ float swc[48];
    __shared__ float sbc;
    const int n = blockIdx.x, tid = threadIdx.x;

    if (tid < 48) swc[tid] = rw[tid];
    if (tid == 0) sbc = rb[0];

    const float4 p = g_roi[n];   // x1, y1, bw, bh
    const int b = n >> 4;
    const int ph = tid >> 4, pw = tid & 15;

    const int hs = (int)fminf(floorf((float)ph * p.w) + p.y, 416.f);
    const int he = (int)fminf(ceilf((float)(ph + 1) * p.w) + p.y, 416.f);
    const int wsb = (int)fminf(floorf((float)pw * p.z) + p.x, 416.f);
    const int web = (int)fminf(ceilf((float)(pw + 1) * p.z) + p.x, 416.f);

    float m0, m1, m2;
    if (he > hs && web > wsb) {
        m0 = m1 = m2 = -3.4e38f;
        const float* c0 = img + (size_t)b * 3 * 416 * 416;
        for (int yy = hs; yy < he; yy++) {
            const float* row = c0 + yy * 416;
            for (int xx = wsb; xx < web; xx++) {
                m0 = fmaxf(m0, row[xx]);
                m1 = fmaxf(m1, row[xx + 416 * 416]);
                m2 = fmaxf(m2, row[xx + 2 * 416 * 416]);
            }
        }
    } else {
        m0 = m1 = m2 = 0.f;
    }
    pooled[0][ph][pw] = m0;
    pooled[1][ph][pw] = m1;
    pooled[2][ph][pw] = m2;
    __syncthreads();

    if (tid < 169) {
        const int oy = tid / 13, ox = tid % 13;
        float s = sbc;
#pragma unroll
        for (int c = 0; c < 3; c++)
#pragma unroll
            for (int ky = 0; ky < 4; ky++)
#pragma unroll
                for (int kx = 0; kx < 4; kx++)
                    s = fmaf(pooled[c][oy + ky][ox + kx],
                             swc[(c * 4 + ky) * 4 + kx], s);
        yv[tid] = fmaxf(s, 0.f);
    }
    __syncthreads();

    if (tid < 64) {
        float s = b2[tid];
        const float* wr = w2 + tid * 169;
        for (int pp = 0; pp < 169; pp++) s = fmaf(yv[pp], __ldg(&wr[pp]), s);
        out[(size_t)n * 64 + tid] = fmaxf(s, 0.f);
    }
}

// ---------------------------------------------------------------------------
extern "C" void kernel_launch(void* const* d_in, const int* in_sizes, int n_in,
                              void* d_out, int out_size) {
    const float* img     = (const float*)d_in[0];
    const float* conv1_w = (const float*)d_in[1];
    const float* conv1_b = (const float*)d_in[2];
    const float* conv2_w = (const float*)d_in[3];
    const float* conv2_b = (const float*)d_in[4];
    const float* fc1_w   = (const float*)d_in[5];
    const float* fc1_b   = (const float*)d_in[6];
    const float* roi_w   = (const float*)d_in[7];
    const float* roi_b   = (const float*)d_in[8];
    const float* fc2_w   = (const float*)d_in[9];
    const float* fc2_b   = (const float*)d_in[10];
    float* out = (float*)d_out;

    dim3 g1(7, 13, 64);    // pooled 206: x covers 7*32=224, y 13*16=208
    conv1_kernel<<<g1, 256>>>(img, conv1_w, conv1_b);

    dim3 g2(7, 7, 64);     // pooled 101: 7*16=112 both dims
    conv2_kernel<<<g2, 256>>>(conv2_w, conv2_b);

    fc1_kernel<<<101, 256>>>(fc1_w);
    fc1_finalize_boxes<<<64, 256>>>(fc1_b);
    roi_kernel<<<1024, 256>>>(img, roi_w, roi_b, fc2_w, fc2_b, out);
}